// round 17
// baseline (speedup 1.0000x reference)
#include <cuda_runtime.h>
#include <cuda_bf16.h>
#include <cuda_fp16.h>
#include <cstdint>

#define N_NODES 100000
#define DIM 64
#define N_EDGES 1200000
#define CAP 64
#define M_TILE 128
#define N_TILES ((N_NODES + M_TILE - 1) / M_TILE)   // 782
#define GEMM_GRID 148                                // 1 persistent block/SM

// ---- scratch (__device__ globals) ------------------------------------------
__device__ __align__(16) __half g_th[N_NODES * DIM];   // neighbor features, fp16
__device__ __align__(16) float  g_acc[N_NODES * DIM];
__device__ int   g_cnt[N_NODES];
__device__ __align__(16) int2 g_cw[(size_t)N_NODES * CAP];
__device__ uint2 g_wbf[3 * 2 * 4 * 16 * 32];       // B fragments

// ---------------------------------------------------------------------------
__device__ __forceinline__ uint32_t pack_bf2(float a, float b)
{
    __nv_bfloat162 h = __floats2bfloat162_rn(a, b);
    return *(uint32_t*)&h;
}

// ---------------------------------------------------------------------------
// Weight fragment prep (once per call). mma m16n8k16 .row.col B operand.
// ---------------------------------------------------------------------------
__global__ void k_wprep(const float* __restrict__ Ws, const float* __restrict__ Wn)
{
    const int idx = blockIdx.x * 256 + threadIdx.x;
    if (idx >= 3 * 2 * 4 * 16 * 32) return;
    const int lane = idx & 31;
    const int n8   = (idx >> 5) & 15;
    const int q    = (idx >> 9) & 3;
    const int s    = (idx >> 11) & 1;
    const int l    = idx >> 12;
    const int g  = lane >> 2, tg = lane & 3;
    const int n  = n8 * 8 + g;
    const int k0 = q * 16;

    const float* W = (n < DIM) ? (Ws + l * DIM * DIM) : (Wn + l * DIM * DIM - DIM);
    float v[4];
    v[0] = W[(k0 + tg * 2) * DIM + n];
    v[1] = W[(k0 + tg * 2 + 1) * DIM + n];
    v[2] = W[(k0 + 8 + tg * 2) * DIM + n];
    v[3] = W[(k0 + 8 + tg * 2 + 1) * DIM + n];
    if (s == 1) {
        #pragma unroll
        for (int i = 0; i < 4; i++)
            v[i] = v[i] - __bfloat162float(__float2bfloat16(v[i]));
    }
    g_wbf[idx] = make_uint2(pack_bf2(v[0], v[1]), pack_bf2(v[2], v[3]));
}

// ---------------------------------------------------------------------------
// bucketed edge build (row-major buckets)
// ---------------------------------------------------------------------------
__global__ void k_fill(const int* __restrict__ row, const int* __restrict__ col,
                       const float* __restrict__ ew)
{
    int e = blockIdx.x * blockDim.x + threadIdx.x;
    if (e >= N_EDGES) return;
    const int r = row[e];
    const int p = atomicAdd(&g_cnt[r], 1);
    if (p < CAP)
        g_cw[(size_t)r * CAP + p] = make_int2(col[e], __float_as_int(ew[e]));
}

// ---------------------------------------------------------------------------
__device__ __forceinline__ void mma_bf16(float* c, const uint32_t* a, uint2 b)
{
    asm volatile(
        "mma.sync.aligned.m16n8k16.row.col.f32.bf16.bf16.f32 "
        "{%0,%1,%2,%3}, {%4,%5,%6,%7}, {%8,%9}, {%0,%1,%2,%3};"
        : "+f"(c[0]), "+f"(c[1]), "+f"(c[2]), "+f"(c[3])
        : "r"(a[0]), "r"(a[1]), "r"(a[2]), "r"(a[3]), "r"(b.x), "r"(b.y));
}
__device__ __forceinline__ void ldsm4(uint32_t* a, uint32_t addr)
{
    asm volatile("ldmatrix.sync.aligned.m8n8.x4.shared.b16 {%0,%1,%2,%3}, [%4];"
                 : "=r"(a[0]), "=r"(a[1]), "=r"(a[2]), "=r"(a[3]) : "r"(addr));
}

#define SA_PITCH 144
#define SA_SPLIT (M_TILE * SA_PITCH)

// ---------------------------------------------------------------------------
// K1: persistent tensor-core dual GEMM (bf16 3-split via mma.sync).
//   acc[m,j] = relu?(in)@Ws + b  (fp32) ;  t_h[m,j] = relu?(in)@Wn  (fp16)
// ---------------------------------------------------------------------------
__global__ void __launch_bounds__(256, 1) sage_gemm_mma(
    const float* __restrict__ in,
    float* __restrict__ acc,
    __half* __restrict__ th,
    const uint2* __restrict__ wb,
    const float* __restrict__ bias,
    int relu_in)
{
    __shared__ __align__(16) unsigned char sA[2 * SA_SPLIT];

    const int tid  = threadIdx.x;
    const int wid  = tid >> 5;
    const int lane = tid & 31;
    const int wm   = wid >> 2;
    const int wn   = wid & 3;
    const int g    = lane >> 2;
    const int tg   = lane & 3;

    uint2 bw[2][4][4];
    #pragma unroll
    for (int s = 0; s < 2; s++)
        #pragma unroll
        for (int q = 0; q < 4; q++)
            #pragma unroll
            for (int n8 = 0; n8 < 4; n8++)
                bw[s][q][n8] = wb[(((s * 4 + q) * 16) + wn * 4 + n8) * 32 + lane];

    float2 bias2[4];
    if (wn < 2) {
        #pragma unroll
        for (int n8 = 0; n8 < 4; n8++)
            bias2[n8] = *(const float2*)(bias + wn * 32 + n8 * 8 + tg * 2);
    }

    uint32_t sa_base;
    asm("{ .reg .u64 u; cvta.to.shared.u64 u, %1; cvt.u32.u64 %0, u; }"
        : "=r"(sa_base) : "l"(sA));
    const int r    = lane & 7;
    const int row8 = ((lane >> 3) & 1) * 8;
    const int koff = (lane >> 4) * 16;
    const uint32_t abase = sa_base + (wm * 64 + row8 + r) * SA_PITCH + koff;

    const float4* in4 = (const float4*)in;

    for (int tile = blockIdx.x; tile < N_TILES; tile += gridDim.x) {
        const int node0 = tile * M_TILE;

        #pragma unroll
        for (int i = tid; i < M_TILE * (DIM / 4); i += 256) {
            const int node = i >> 4;
            const int kq   = i & 15;
            float4 v = make_float4(0.f, 0.f, 0.f, 0.f);
            if (node0 + node < N_NODES)
                v = in4[(size_t)(node0 + node) * (DIM / 4) + kq];
            if (relu_in) {
                v.x = fmaxf(v.x, 0.f); v.y = fmaxf(v.y, 0.f);
                v.z = fmaxf(v.z, 0.f); v.w = fmaxf(v.w, 0.f);
            }
            float hx = __bfloat162float(__float2bfloat16(v.x));
            float hy = __bfloat162float(__float2bfloat16(v.y));
            float hz = __bfloat162float(__float2bfloat16(v.z));
            float hw = __bfloat162float(__float2bfloat16(v.w));
            uint2 hi = make_uint2(pack_bf2(v.x, v.y), pack_bf2(v.z, v.w));
            uint2 lo = make_uint2(pack_bf2(v.x - hx, v.y - hy),
                                  pack_bf2(v.z - hz, v.w - hw));
            *(uint2*)(sA + node * SA_PITCH + kq * 8)            = hi;
            *(uint2*)(sA + SA_SPLIT + node * SA_PITCH + kq * 8) = lo;
        }
        __syncthreads();

        float c[4][4][4];
        #pragma unroll
        for (int mf = 0; mf < 4; mf++)
            #pragma unroll
            for (int n8 = 0; n8 < 4; n8++)
                #pragma unroll
                for (int e = 0; e < 4; e++) c[mf][n8][e] = 0.f;

        #pragma unroll
        for (int q = 0; q < 4; q++) {
            uint32_t ah[4][4], al[4][4];
            #pragma unroll
            for (int mf = 0; mf < 4; mf++) {
                ldsm4(ah[mf], abase + mf * 16 * SA_PITCH + q * 32);
                ldsm4(al[mf], abase + SA_SPLIT + mf * 16 * SA_PITCH + q * 32);
            }
            #pragma unroll
            for (int n8 = 0; n8 < 4; n8++) {
                #pragma unroll
                for (int mf = 0; mf < 4; mf++) {
                    mma_bf16(c[mf][n8], ah[mf], bw[0][q][n8]);
                    mma_bf16(c[mf][n8], al[mf], bw[0][q][n8]);
                    mma_bf16(c[mf][n8], ah[mf], bw[1][q][n8]);
                }
            }
        }

        const bool self = (wn < 2);
        #pragma unroll
        for (int n8 = 0; n8 < 4; n8++) {
            const int jj   = wn * 32 + n8 * 8 + tg * 2;
            #pragma unroll
            for (int mf = 0; mf < 4; mf++) {
                const int nd = node0 + wm * 64 + mf * 16 + g;
                if (self) {
                    const float bx = bias2[n8].x, by = bias2[n8].y;
                    if (nd < N_NODES)
                        *(float2*)(acc + (size_t)nd * DIM + jj) =
                            make_float2(c[mf][n8][0] + bx, c[mf][n8][1] + by);
                    if (nd + 8 < N_NODES)
                        *(float2*)(acc + (size_t)(nd + 8) * DIM + jj) =
                            make_float2(c[mf][n8][2] + bx, c[mf][n8][3] + by);
                } else {
                    const int jloc = jj - 64;
                    if (nd < N_NODES)
                        *(__half2*)(th + (size_t)nd * DIM + jloc) =
                            __floats2half2_rn(c[mf][n8][0], c[mf][n8][1]);
                    if (nd + 8 < N_NODES)
                        *(__half2*)(th + (size_t)(nd + 8) * DIM + jloc) =
                            __floats2half2_rn(c[mf][n8][2], c[mf][n8][3]);
                }
            }
        }
        __syncthreads();
    }
}

// ---------------------------------------------------------------------------
// K2: gather — 16 lanes/node, 128-thread blocks, reg-capped for full occupancy
// (latency-bound: resident warps are the lever). 32-bit t-row offsets; acc
// load hoisted above the edge loop to overlap its latency.
// ---------------------------------------------------------------------------
__device__ __forceinline__ void fma_h4(float4& s, float w, uint2 v)
{
    const float2 f0 = __half22float2(*(const __half2*)&v.x);
    const float2 f1 = __half22float2(*(const __half2*)&v.y);
    s.x = fmaf(w, f0.x, s.x); s.y = fmaf(w, f0.y, s.y);
    s.z = fmaf(w, f1.x, s.z); s.w = fmaf(w, f1.y, s.w);
}

__global__ void __launch_bounds__(128, 16) sage_gather(
    const __half* __restrict__ th,
    const float* __restrict__ acc,
    float* __restrict__ out,
    int relu_out)
{
    const int node = blockIdx.x * 8 + (threadIdx.x >> 4);
    const unsigned lane = threadIdx.x & 15;
    const int cnt  = min(g_cnt[node], CAP);

    const int2* cw = g_cw + (size_t)node * CAP;
    const uint2* t2 = (const uint2*)th;     // 16 uint2 per node row

    // hoisted: independent of the edge loop, overlaps gather latency
    float4 a_out = ((const float4*)acc)[(size_t)node * 16 + lane];

    float4 s0 = make_float4(0.f, 0.f, 0.f, 0.f);
    float4 s1 = make_float4(0.f, 0.f, 0.f, 0.f);

    int k = 0;
    for (; k + 4 <= cnt; k += 4) {
        const int4 a = *(const int4*)(cw + k);
        const int4 b = *(const int4*)(cw + k + 2);
        // 32-bit row offsets (node*16+lane < 2^21)
        const uint2 v0 = __ldg(t2 + (((unsigned)a.x << 4) | lane));
        const uint2 v1 = __ldg(t2 + (((unsigned)a.z << 4) | lane));
        const uint2 v2 = __ldg(t2 + (((unsigned)b.x << 4) | lane));
        const uint2 v3 = __ldg(t2 + (((unsigned)b.z << 4) | lane));
        fma_h4(s0, __int_as_float(a.y), v0);
        fma_h4(s1, __int_as_float(a.w), v1);
        fma_h4(s0, __int_as_float(b.y), v2);
        fma_h4(s1, __int_as_float(b.w), v3);
    }
    for (; k < cnt; k++) {
        const int2 c = cw[k];
        const uint2 v = __ldg(t2 + (((unsigned)c.x << 4) | lane));
        fma_h4(s0, __int_as_float(c.y), v);
    }

    a_out.x += s0.x + s1.x; a_out.y += s0.y + s1.y;
    a_out.z += s0.z + s1.z; a_out.w += s0.w + s1.w;
    if (relu_out) {
        a_out.x = fmaxf(a_out.x, 0.f); a_out.y = fmaxf(a_out.y, 0.f);
        a_out.z = fmaxf(a_out.z, 0.f); a_out.w = fmaxf(a_out.w, 0.f);
    }
    ((float4*)out)[(size_t)node * 16 + lane] = a_out;
}

// ---------------------------------------------------------------------------
extern "C" void kernel_launch(void* const* d_in, const int* in_sizes, int n_in,
                              void* d_out, int out_size)
{
    const float* x     = (const float*)d_in[0];
    const int*   ei    = (const int*)  d_in[1];
    const float* ew    = (const float*)d_in[2];
    const float* Wself = (const float*)d_in[3];
    const float* Wngh  = (const float*)d_in[4];
    const float* bias  = (const float*)d_in[5];
    float* out = (float*)d_out;

    const int* row = ei;
    const int* col = ei + N_EDGES;

    float *acc_ptr;
    __half* th_ptr;
    uint2* wb_ptr;
    void *cnt_p;
    cudaGetSymbolAddress((void**)&th_ptr,  g_th);
    cudaGetSymbolAddress((void**)&acc_ptr, g_acc);
    cudaGetSymbolAddress((void**)&wb_ptr,  g_wbf);
    cudaGetSymbolAddress(&cnt_p, g_cnt);

    cudaStream_t s2;
    cudaEvent_t evF, evJ;
    cudaStreamCreateWithFlags(&s2, cudaStreamNonBlocking);
    cudaEventCreateWithFlags(&evF, cudaEventDisableTiming);
    cudaEventCreateWithFlags(&evJ, cudaEventDisableTiming);

    const int GATHER_BLOCKS = N_NODES / 8;   // 12500 (128-thread blocks)
    const int WB_L = 2 * 4 * 16 * 32;

    // wprep first (GEMM-L0 depends on it)
    k_wprep<<<(3 * 2 * 4 * 16 * 32 + 255) / 256, 256>>>(Wself, Wngh);

    // fork: edge-bucket build on s2, concurrent with GEMM layer 0
    cudaEventRecord(evF, 0);
    cudaStreamWaitEvent(s2, evF, 0);
    cudaMemsetAsync(cnt_p, 0, N_NODES * sizeof(int), s2);
    k_fill<<<(N_EDGES + 255) / 256, 256, 0, s2>>>(row, col, ew);
    cudaEventRecord(evJ, s2);

    // layer 0 GEMM (independent of build)
    sage_gemm_mma<<<GEMM_GRID, 256>>>(x, acc_ptr, th_ptr, wb_ptr, bias, 0);

    // join: gather needs the buckets
    cudaStreamWaitEvent(0, evJ, 0);
    sage_gather<<<GATHER_BLOCKS, 128>>>(th_ptr, acc_ptr, acc_ptr, 0);

    sage_gemm_mma<<<GEMM_GRID, 256>>>(acc_ptr, acc_ptr, th_ptr,
                                      wb_ptr + WB_L, bias + DIM, 1);
    sage_gather<<<GATHER_BLOCKS, 128>>>(th_ptr, acc_ptr, acc_ptr, 0);

    sage_gemm_mma<<<GEMM_GRID, 256>>>(acc_ptr, acc_ptr, th_ptr,
                                      wb_ptr + 2 * WB_L, bias + 2 * DIM, 1);
    sage_gather<<<GATHER_BLOCKS, 128>>>(th_ptr, acc_ptr, out, 1);
}